// round 3
// baseline (speedup 1.0000x reference)
#include <cuda_runtime.h>
#include <cstdint>
#include <cstddef>

// Problem constants
#define NW    720
#define LTOK  144
#define DIM   192
#define NHEAD 6
#define HD    32
#define TOW   240
#define SCALE 0.17677669529663687f   // 32^-0.5

// ---------------------------------------------------------------------------
// Scratch
// ---------------------------------------------------------------------------
__device__ float g_qkv[(size_t)NW * 3 * NHEAD * LTOK * HD];  // [w][t][h][l][d]
__device__ float g_bias[(size_t)TOW * NHEAD * LTOK * LTOK];  // [tow*6+h][i*144+j]
__device__ float g_att[(size_t)NW * LTOK * DIM];             // [w][l][h*32+d]

__device__ __forceinline__ int posidx(int a, int b) {
    int za = a / 72, ha = (a % 72) / 12, wa = a % 12;
    int zb = b / 72, hb = (b % 72) / 12, wb = b % 12;
    return 828 * (za + 2 * zb) + 23 * (ha + 6 * hb) + (wa - wb + 11);
}

// ---------------------------------------------------------------------------
// K0: bias gather/transpose
// ---------------------------------------------------------------------------
__global__ void bias_gather_kernel(const float* __restrict__ table) {
    __shared__ float tile[32][241];
    const int ij0 = blockIdx.x * 32;
    const int tt0 = blockIdx.y * 240;
    const int tid = threadIdx.x;

    for (int e = tid; e < 32 * 240; e += 256) {
        int ii = e / 240, tt = e % 240;
        int ij = ij0 + ii;
        int a = ij / LTOK, b = ij % LTOK;
        tile[ii][tt] = table[(size_t)posidx(a, b) * (TOW * NHEAD) + tt0 + tt];
    }
    __syncthreads();
    for (int e = tid; e < 32 * 240; e += 256) {
        int tt = e / 32, c = e % 32;
        g_bias[(size_t)(tt0 + tt) * (LTOK * LTOK) + ij0 + c] = tile[c][tt];
    }
}

// ---------------------------------------------------------------------------
// K1/K3 GEMM: C[m][n] = sum_k A[m][k]*B[n][k] + bias[n]
// BM=128, BN=64, KC=48. 128 threads, 8x8 micro-tile.
// smem k-major: As[k][m] (stride 132), Bs[k][n] (stride 68) -> fragment loads
// are 2x LDS.128 each; A-frag is warp-broadcast. FFMA-bound.
// ---------------------------------------------------------------------------
#define BM 128
#define BN 64
#define KC 48
#define LDAM 132
#define LDBN 68

template <int MODE>
__global__ __launch_bounds__(128)
void gemm_kernel(const float* __restrict__ Ain,
                 const float* __restrict__ B,
                 const float* __restrict__ bias,
                 float* __restrict__ C) {
    __shared__ float As[KC * LDAM];   // [k][m]
    __shared__ float Bs[KC * LDBN];   // [k][n]

    const float* A = (MODE == 0) ? g_att : Ain;

    const int tid = threadIdx.x;
    const int m0 = blockIdx.y * BM;
    const int n0 = blockIdx.x * BN;

    const int tx = tid % 8, ty = tid / 8;
    const int mrow = ty * 8, ncol = tx * 8;

    float acc[8][8];
#pragma unroll
    for (int i = 0; i < 8; i++)
#pragma unroll
        for (int j = 0; j < 8; j++) acc[i][j] = 0.0f;

    for (int kc = 0; kc < 192; kc += KC) {
        if (kc) __syncthreads();
        // A chunk: 128 rows x 12 float4 along k, transposed into As[k][m]
        for (int e = tid; e < BM * 12; e += 128) {
            int m = e / 12, k4 = e % 12;
            float4 v = *reinterpret_cast<const float4*>(
                A + (size_t)(m0 + m) * 192 + kc + k4 * 4);
            As[(k4 * 4 + 0) * LDAM + m] = v.x;
            As[(k4 * 4 + 1) * LDAM + m] = v.y;
            As[(k4 * 4 + 2) * LDAM + m] = v.z;
            As[(k4 * 4 + 3) * LDAM + m] = v.w;
        }
        // B chunk: 64 rows x 12 float4 -> Bs[k][n]
        for (int e = tid; e < BN * 12; e += 128) {
            int n = e / 12, k4 = e % 12;
            float4 v = *reinterpret_cast<const float4*>(
                B + (size_t)(n0 + n) * 192 + kc + k4 * 4);
            Bs[(k4 * 4 + 0) * LDBN + n] = v.x;
            Bs[(k4 * 4 + 1) * LDBN + n] = v.y;
            Bs[(k4 * 4 + 2) * LDBN + n] = v.z;
            Bs[(k4 * 4 + 3) * LDBN + n] = v.w;
        }
        __syncthreads();

#pragma unroll 4
        for (int k = 0; k < KC; k++) {
            const float* Ak = As + k * LDAM + mrow;
            const float* Bk = Bs + k * LDBN + ncol;
            float4 a0 = *reinterpret_cast<const float4*>(Ak);
            float4 a1 = *reinterpret_cast<const float4*>(Ak + 4);
            float4 b0 = *reinterpret_cast<const float4*>(Bk);
            float4 b1 = *reinterpret_cast<const float4*>(Bk + 4);
            float a[8] = {a0.x, a0.y, a0.z, a0.w, a1.x, a1.y, a1.z, a1.w};
            float b[8] = {b0.x, b0.y, b0.z, b0.w, b1.x, b1.y, b1.z, b1.w};
#pragma unroll
            for (int i = 0; i < 8; i++)
#pragma unroll
                for (int j = 0; j < 8; j++) acc[i][j] += a[i] * b[j];
        }
    }

    float4 bb0 = *reinterpret_cast<const float4*>(bias + n0 + ncol);
    float4 bb1 = *reinterpret_cast<const float4*>(bias + n0 + ncol + 4);

#pragma unroll
    for (int i = 0; i < 8; i++) {
        int m = m0 + mrow + i;
        float4 o0, o1;
        o0.x = acc[i][0] + bb0.x; o0.y = acc[i][1] + bb0.y;
        o0.z = acc[i][2] + bb0.z; o0.w = acc[i][3] + bb0.w;
        o1.x = acc[i][4] + bb1.x; o1.y = acc[i][5] + bb1.y;
        o1.z = acc[i][6] + bb1.z; o1.w = acc[i][7] + bb1.w;
        if (MODE == 0) {
            float4* dst = reinterpret_cast<float4*>(C + (size_t)m * DIM + n0 + ncol);
            dst[0] = o0;
            dst[1] = o1;
        } else {
            int w = m / LTOK, l = m % LTOK;
            int c0 = n0 + ncol;
            {
                int t = c0 / DIM, rem = c0 % DIM;
                int h = rem / HD, d = rem % HD;
                size_t off = ((((size_t)w * 3 + t) * NHEAD + h) * LTOK + l) * HD + d;
                *reinterpret_cast<float4*>(g_qkv + off) = o0;
            }
            {
                int c1 = c0 + 4;
                int t = c1 / DIM, rem = c1 % DIM;
                int h = rem / HD, d = rem % HD;
                size_t off = ((((size_t)w * 3 + t) * NHEAD + h) * LTOK + l) * HD + d;
                *reinterpret_cast<float4*>(g_qkv + off) = o1;
            }
        }
    }
}

// ---------------------------------------------------------------------------
// K2: fused attention. Block = (tow, head), loops 3 windows sharing a bias.
// 288 threads: thread t -> row i = t/2, j-half = t%2 (72 keys each).
// Partial (acc, lsum) combined with lane-pair shfl_xor(1) (deterministic:
// both lanes compute a+b with identical operand order). Single-pass softmax
// (logits are O(0.1); shift-invariant).
// ---------------------------------------------------------------------------
__global__ __launch_bounds__(288)
void attn_kernel(const float* __restrict__ mask) {
    __shared__ float4 ks4[LTOK * 8];
    __shared__ float4 vs4[LTOK * 8];

    const int bx = blockIdx.x;
    const int tow = bx / NHEAD;
    const int h = bx % NHEAD;
    const int tid = threadIdx.x;
    const int i = tid >> 1;        // query row
    const int half = tid & 1;      // j-half

    for (int wrep = 0; wrep < 3; wrep++) {
        const int w = tow + wrep * TOW;
        const float4* kg = reinterpret_cast<const float4*>(
            g_qkv + (((size_t)w * 3 + 1) * NHEAD + h) * (LTOK * HD));
        const float4* vg = reinterpret_cast<const float4*>(
            g_qkv + (((size_t)w * 3 + 2) * NHEAD + h) * (LTOK * HD));

        __syncthreads();
        for (int e = tid; e < LTOK * 8; e += 288) {
            ks4[e] = kg[e];
            vs4[e] = vg[e];
        }
        __syncthreads();

        const float4* qg = reinterpret_cast<const float4*>(
            g_qkv + (((size_t)w * 3 + 0) * NHEAD + h) * (LTOK * HD) + i * HD);
        float4 q[8];
#pragma unroll
        for (int d = 0; d < 8; d++) {
            q[d] = qg[d];
            q[d].x *= SCALE; q[d].y *= SCALE; q[d].z *= SCALE; q[d].w *= SCALE;
        }
        const float4* brow = reinterpret_cast<const float4*>(
            g_bias + ((size_t)tow * NHEAD + h) * (LTOK * LTOK) + i * LTOK);
        const float4* mrow = reinterpret_cast<const float4*>(
            mask + ((size_t)w * LTOK + i) * LTOK);

        float4 acc[8];
#pragma unroll
        for (int d = 0; d < 8; d++) acc[d] = make_float4(0.f, 0.f, 0.f, 0.f);
        float lsum = 0.0f;

        const int j4lo = half * 18;        // 18 float4 groups = 72 keys
        for (int j4 = j4lo; j4 < j4lo + 18; j4++) {
            float4 b4 = brow[j4];
            float4 m4 = mrow[j4];
            float bm[4] = {b4.x + m4.x, b4.y + m4.y, b4.z + m4.z, b4.w + m4.w};
#pragma unroll
            for (int u = 0; u < 4; u++) {
                const int j = j4 * 4 + u;
                const float4* kr = &ks4[j * 8];
                float s0 = 0.f, s1 = 0.f, s2 = 0.f, s3 = 0.f;
#pragma unroll
                for (int d = 0; d < 8; d += 2) {
                    float4 k0 = kr[d], k1 = kr[d + 1];
                    s0 += q[d].x * k0.x + q[d].y * k0.y;
                    s1 += q[d].z * k0.z + q[d].w * k0.w;
                    s2 += q[d + 1].x * k1.x + q[d + 1].y * k1.y;
                    s3 += q[d + 1].z * k1.z + q[d + 1].w * k1.w;
                }
                float p = __expf((s0 + s1) + (s2 + s3) + bm[u]);
                lsum += p;
                const float4* vr = &vs4[j * 8];
#pragma unroll
                for (int d = 0; d < 8; d++) {
                    float4 vv = vr[d];
                    acc[d].x += p * vv.x;
                    acc[d].y += p * vv.y;
                    acc[d].z += p * vv.z;
                    acc[d].w += p * vv.w;
                }
            }
        }

        // combine the two j-halves (lane pairs are in-warp: tid and tid^1)
#pragma unroll
        for (int d = 0; d < 8; d++) {
            acc[d].x += __shfl_xor_sync(0xFFFFFFFFu, acc[d].x, 1);
            acc[d].y += __shfl_xor_sync(0xFFFFFFFFu, acc[d].y, 1);
            acc[d].z += __shfl_xor_sync(0xFFFFFFFFu, acc[d].z, 1);
            acc[d].w += __shfl_xor_sync(0xFFFFFFFFu, acc[d].w, 1);
        }
        lsum += __shfl_xor_sync(0xFFFFFFFFu, lsum, 1);

        const float rinv = 1.0f / lsum;
        float4* orow = reinterpret_cast<float4*>(
            g_att + ((size_t)w * LTOK + i) * DIM + h * HD);
        // split the store: half 0 writes d=0..3, half 1 writes d=4..7
#pragma unroll
        for (int d = 0; d < 4; d++) {
            int dd = half * 4 + d;
            float4 o = acc[dd];
            o.x *= rinv; o.y *= rinv; o.z *= rinv; o.w *= rinv;
            orow[dd] = o;
        }
    }
}

// ---------------------------------------------------------------------------
// Launch. Inputs: 0 x, 1 mask, 2 w1, 3 b1, 4 w2, 5 b2, 6 bias_table
// ---------------------------------------------------------------------------
extern "C" void kernel_launch(void* const* d_in, const int* in_sizes, int n_in,
                              void* d_out, int out_size) {
    const float* x     = (const float*)d_in[0];
    const float* mask  = (const float*)d_in[1];
    const float* w1    = (const float*)d_in[2];
    const float* b1    = (const float*)d_in[3];
    const float* w2    = (const float*)d_in[4];
    const float* b2    = (const float*)d_in[5];
    const float* table = (const float*)d_in[6];
    float* out = (float*)d_out;

    bias_gather_kernel<<<dim3(648, 6), 256>>>(table);
    gemm_kernel<1><<<dim3(576 / BN, (NW * LTOK) / BM), 128>>>(x, w1, b1, nullptr);
    attn_kernel<<<TOW * NHEAD, 288>>>(mask);
    gemm_kernel<0><<<dim3(DIM / BN, (NW * LTOK) / BM), 128>>>(nullptr, w2, b2, out);
}

// round 4
// speedup vs baseline: 1.1500x; 1.1500x over previous
#include <cuda_runtime.h>
#include <cstdint>
#include <cstddef>

// Problem constants
#define NW    720
#define LTOK  144
#define DIM   192
#define NHEAD 6
#define HD    32
#define TOW   240
#define SCALE 0.17677669529663687f   // 32^-0.5

// ---------------------------------------------------------------------------
// Scratch
// ---------------------------------------------------------------------------
__device__ float g_qkv[(size_t)NW * 3 * NHEAD * LTOK * HD];  // [w][t][h][l][d]
__device__ float g_bias[(size_t)TOW * NHEAD * LTOK * LTOK];  // [tow*6+h][i*144+j]
__device__ float g_att[(size_t)NW * LTOK * DIM];             // [w][l][h*32+d]

__device__ __forceinline__ int posidx(int a, int b) {
    int za = a / 72, ha = (a % 72) / 12, wa = a % 12;
    int zb = b / 72, hb = (b % 72) / 12, wb = b % 12;
    return 828 * (za + 2 * zb) + 23 * (ha + 6 * hb) + (wa - wb + 11);
}

// ---------------------------------------------------------------------------
// K0: bias gather/transpose
// ---------------------------------------------------------------------------
__global__ void bias_gather_kernel(const float* __restrict__ table) {
    __shared__ float tile[32][241];
    const int ij0 = blockIdx.x * 32;
    const int tt0 = blockIdx.y * 240;
    const int tid = threadIdx.x;

    for (int e = tid; e < 32 * 240; e += 256) {
        int ii = e / 240, tt = e % 240;
        int ij = ij0 + ii;
        int a = ij / LTOK, b = ij % LTOK;
        tile[ii][tt] = table[(size_t)posidx(a, b) * (TOW * NHEAD) + tt0 + tt];
    }
    __syncthreads();
    for (int e = tid; e < 32 * 240; e += 256) {
        int tt = e / 32, c = e % 32;
        g_bias[(size_t)(tt0 + tt) * (LTOK * LTOK) + ij0 + c] = tile[c][tt];
    }
}

// ---------------------------------------------------------------------------
// K1/K3 GEMM (exact R2 version, measured 217us for MODE 0):
// C[m][n] = sum_k A[m][k]*B[n][k] + bias[n]
// BM=128, BN=64, KC=48, 128 threads, 8x8 micro-tile, row-major padded smem.
// ---------------------------------------------------------------------------
#define BM 128
#define BN 64
#define KC 48
#define LDP 51

template <int MODE>
__global__ __launch_bounds__(128, 4)
void gemm_kernel(const float* __restrict__ Ain,
                 const float* __restrict__ B,
                 const float* __restrict__ bias,
                 float* __restrict__ C) {
    __shared__ float As[BM * LDP];
    __shared__ float Bs[BN * LDP];

    const float* A = (MODE == 0) ? g_att : Ain;

    const int tid = threadIdx.x;
    const int m0 = blockIdx.y * BM;
    const int n0 = blockIdx.x * BN;

    const int tx = tid % 8, ty = tid / 8;
    const int mrow = ty * 8, ncol = tx * 8;

    float acc[8][8];
#pragma unroll
    for (int i = 0; i < 8; i++)
#pragma unroll
        for (int j = 0; j < 8; j++) acc[i][j] = 0.0f;

    for (int kc = 0; kc < 192; kc += KC) {
        if (kc) __syncthreads();
        for (int e = tid; e < BM * 12; e += 128) {
            int m = e / 12, k4 = e % 12;
            float4 v = *reinterpret_cast<const float4*>(
                A + (size_t)(m0 + m) * 192 + kc + k4 * 4);
            float* dst = As + m * LDP + k4 * 4;
            dst[0] = v.x; dst[1] = v.y; dst[2] = v.z; dst[3] = v.w;
        }
        for (int e = tid; e < BN * 12; e += 128) {
            int n = e / 12, k4 = e % 12;
            float4 v = *reinterpret_cast<const float4*>(
                B + (size_t)(n0 + n) * 192 + kc + k4 * 4);
            float* dst = Bs + n * LDP + k4 * 4;
            dst[0] = v.x; dst[1] = v.y; dst[2] = v.z; dst[3] = v.w;
        }
        __syncthreads();

#pragma unroll 2
        for (int k = 0; k < KC; k++) {
            float a[8], b[8];
#pragma unroll
            for (int i = 0; i < 8; i++) a[i] = As[(mrow + i) * LDP + k];
#pragma unroll
            for (int j = 0; j < 8; j++) b[j] = Bs[(ncol + j) * LDP + k];
#pragma unroll
            for (int i = 0; i < 8; i++)
#pragma unroll
                for (int j = 0; j < 8; j++) acc[i][j] += a[i] * b[j];
        }
    }

    float4 bb0 = *reinterpret_cast<const float4*>(bias + n0 + ncol);
    float4 bb1 = *reinterpret_cast<const float4*>(bias + n0 + ncol + 4);

#pragma unroll
    for (int i = 0; i < 8; i++) {
        int m = m0 + mrow + i;
        float4 o0, o1;
        o0.x = acc[i][0] + bb0.x; o0.y = acc[i][1] + bb0.y;
        o0.z = acc[i][2] + bb0.z; o0.w = acc[i][3] + bb0.w;
        o1.x = acc[i][4] + bb1.x; o1.y = acc[i][5] + bb1.y;
        o1.z = acc[i][6] + bb1.z; o1.w = acc[i][7] + bb1.w;
        if (MODE == 0) {
            float4* dst = reinterpret_cast<float4*>(C + (size_t)m * DIM + n0 + ncol);
            dst[0] = o0;
            dst[1] = o1;
        } else {
            int w = m / LTOK, l = m % LTOK;
            int c0 = n0 + ncol;
            {
                int t = c0 / DIM, rem = c0 % DIM;
                int h = rem / HD, d = rem % HD;
                size_t off = ((((size_t)w * 3 + t) * NHEAD + h) * LTOK + l) * HD + d;
                *reinterpret_cast<float4*>(g_qkv + off) = o0;
            }
            {
                int c1 = c0 + 4;
                int t = c1 / DIM, rem = c1 % DIM;
                int h = rem / HD, d = rem % HD;
                size_t off = ((((size_t)w * 3 + t) * NHEAD + h) * LTOK + l) * HD + d;
                *reinterpret_cast<float4*>(g_qkv + off) = o1;
            }
        }
    }
}

// ---------------------------------------------------------------------------
// K2: fused attention, 2 query rows per compute thread.
// Block = (tow, head), loops 3 windows sharing one bias matrix.
// 160 threads: all load K/V to smem; threads 0..71 compute rows (t, t+72).
// Each K/V fragment read from smem serves BOTH rows -> total LDS bytes halved
// vs 1-row-per-thread. Single-pass softmax (logits O(0.1); shift-invariant).
// ---------------------------------------------------------------------------
__global__ __launch_bounds__(160)
void attn_kernel(const float* __restrict__ mask) {
    __shared__ float4 ks4[LTOK * 8];
    __shared__ float4 vs4[LTOK * 8];

    const int bx = blockIdx.x;
    const int tow = bx / NHEAD;
    const int h = bx % NHEAD;
    const int tid = threadIdx.x;

    for (int wrep = 0; wrep < 3; wrep++) {
        const int w = tow + wrep * TOW;
        const float4* kg = reinterpret_cast<const float4*>(
            g_qkv + (((size_t)w * 3 + 1) * NHEAD + h) * (LTOK * HD));
        const float4* vg = reinterpret_cast<const float4*>(
            g_qkv + (((size_t)w * 3 + 2) * NHEAD + h) * (LTOK * HD));

        __syncthreads();
        for (int e = tid; e < LTOK * 8; e += 160) {
            ks4[e] = kg[e];
            vs4[e] = vg[e];
        }
        __syncthreads();

        if (tid < 72) {
            const int i0 = tid;
            const int i1 = tid + 72;
            const float4* qbase = reinterpret_cast<const float4*>(
                g_qkv + (((size_t)w * 3 + 0) * NHEAD + h) * (LTOK * HD));
            float4 q0[8], q1[8];
#pragma unroll
            for (int d = 0; d < 8; d++) {
                q0[d] = qbase[i0 * 8 + d];
                q0[d].x *= SCALE; q0[d].y *= SCALE; q0[d].z *= SCALE; q0[d].w *= SCALE;
                q1[d] = qbase[i1 * 8 + d];
                q1[d].x *= SCALE; q1[d].y *= SCALE; q1[d].z *= SCALE; q1[d].w *= SCALE;
            }
            const float4* bbase = reinterpret_cast<const float4*>(
                g_bias + ((size_t)tow * NHEAD + h) * (LTOK * LTOK));
            const float4* mbase = reinterpret_cast<const float4*>(
                mask + (size_t)w * LTOK * LTOK);
            const float4* brow0 = bbase + i0 * 36;
            const float4* brow1 = bbase + i1 * 36;
            const float4* mrow0 = mbase + i0 * 36;
            const float4* mrow1 = mbase + i1 * 36;

            float4 acc0[8], acc1[8];
#pragma unroll
            for (int d = 0; d < 8; d++) {
                acc0[d] = make_float4(0.f, 0.f, 0.f, 0.f);
                acc1[d] = make_float4(0.f, 0.f, 0.f, 0.f);
            }
            float lsum0 = 0.0f, lsum1 = 0.0f;

            for (int j4 = 0; j4 < 36; j4++) {
                float4 b40 = brow0[j4], m40 = mrow0[j4];
                float4 b41 = brow1[j4], m41 = mrow1[j4];
                float bm0[4] = {b40.x + m40.x, b40.y + m40.y, b40.z + m40.z, b40.w + m40.w};
                float bm1[4] = {b41.x + m41.x, b41.y + m41.y, b41.z + m41.z, b41.w + m41.w};
#pragma unroll
                for (int u = 0; u < 4; u++) {
                    const int j = j4 * 4 + u;
                    const float4* kr = &ks4[j * 8];
                    float s0 = 0.f, s1 = 0.f, t0 = 0.f, t1 = 0.f;
#pragma unroll
                    for (int d = 0; d < 8; d++) {
                        float4 kk = kr[d];
                        s0 += q0[d].x * kk.x + q0[d].y * kk.y;
                        s1 += q0[d].z * kk.z + q0[d].w * kk.w;
                        t0 += q1[d].x * kk.x + q1[d].y * kk.y;
                        t1 += q1[d].z * kk.z + q1[d].w * kk.w;
                    }
                    float p0 = __expf(s0 + s1 + bm0[u]);
                    float p1 = __expf(t0 + t1 + bm1[u]);
                    lsum0 += p0;
                    lsum1 += p1;
                    const float4* vr = &vs4[j * 8];
#pragma unroll
                    for (int d = 0; d < 8; d++) {
                        float4 vv = vr[d];
                        acc0[d].x += p0 * vv.x; acc0[d].y += p0 * vv.y;
                        acc0[d].z += p0 * vv.z; acc0[d].w += p0 * vv.w;
                        acc1[d].x += p1 * vv.x; acc1[d].y += p1 * vv.y;
                        acc1[d].z += p1 * vv.z; acc1[d].w += p1 * vv.w;
                    }
                }
            }
            const float rinv0 = 1.0f / lsum0;
            const float rinv1 = 1.0f / lsum1;
            float4* orow0 = reinterpret_cast<float4*>(
                g_att + ((size_t)w * LTOK + i0) * DIM + h * HD);
            float4* orow1 = reinterpret_cast<float4*>(
                g_att + ((size_t)w * LTOK + i1) * DIM + h * HD);
#pragma unroll
            for (int d = 0; d < 8; d++) {
                float4 o0 = acc0[d];
                o0.x *= rinv0; o0.y *= rinv0; o0.z *= rinv0; o0.w *= rinv0;
                orow0[d] = o0;
                float4 o1 = acc1[d];
                o1.x *= rinv1; o1.y *= rinv1; o1.z *= rinv1; o1.w *= rinv1;
                orow1[d] = o1;
            }
        }
    }
}

// ---------------------------------------------------------------------------
// Launch. Inputs: 0 x, 1 mask, 2 w1, 3 b1, 4 w2, 5 b2, 6 bias_table
// ---------------------------------------------------------------------------
extern "C" void kernel_launch(void* const* d_in, const int* in_sizes, int n_in,
                              void* d_out, int out_size) {
    const float* x     = (const float*)d_in[0];
    const float* mask  = (const float*)d_in[1];
    const float* w1    = (const float*)d_in[2];
    const float* b1    = (const float*)d_in[3];
    const float* w2    = (const float*)d_in[4];
    const float* b2    = (const float*)d_in[5];
    const float* table = (const float*)d_in[6];
    float* out = (float*)d_out;

    bias_gather_kernel<<<dim3(648, 6), 256>>>(table);
    gemm_kernel<1><<<dim3(576 / BN, (NW * LTOK) / BM), 128>>>(x, w1, b1, nullptr);
    attn_kernel<<<TOW * NHEAD, 160>>>(mask);
    gemm_kernel<0><<<dim3(DIM / BN, (NW * LTOK) / BM), 128>>>(nullptr, w2, b2, out);
}

// round 7
// speedup vs baseline: 1.6821x; 1.4627x over previous
#include <cuda_runtime.h>
#include <cuda_bf16.h>
#include <cstdint>
#include <cstddef>

// Problem constants
#define NW    720
#define LTOK  144
#define DIM   192
#define NHEAD 6
#define HD    32
#define TOW   240
#define SCALE 0.17677669529663687f   // 32^-0.5

// ---------------------------------------------------------------------------
// Scratch
// ---------------------------------------------------------------------------
__device__ float g_qkv[(size_t)NW * 3 * NHEAD * LTOK * HD];  // [w][t][h][l][d]
__device__ float g_bias[(size_t)TOW * NHEAD * LTOK * LTOK];  // [tow*6+h][i*144+j]
__device__ float g_att[(size_t)NW * LTOK * DIM];             // [w][l][h*32+d]

__device__ __forceinline__ int posidx(int a, int b) {
    int za = a / 72, ha = (a % 72) / 12, wa = a % 12;
    int zb = b / 72, hb = (b % 72) / 12, wb = b % 12;
    return 828 * (za + 2 * zb) + 23 * (ha + 6 * hb) + (wa - wb + 11);
}

__device__ __forceinline__ uint32_t smem_u32(const void* p) {
    uint32_t a;
    asm("{ .reg .u64 t; cvta.to.shared.u64 t, %1; cvt.u32.u64 %0, t; }"
        : "=r"(a) : "l"(p));
    return a;
}
__device__ __forceinline__ uint32_t pack2(float a, float b) {
    __nv_bfloat162 t = __floats2bfloat162_rn(a, b);
    return *reinterpret_cast<uint32_t*>(&t);
}
__device__ __forceinline__ void ldsm4(uint32_t* r, uint32_t addr) {
    asm volatile("ldmatrix.sync.aligned.m8n8.x4.shared.b16 {%0,%1,%2,%3}, [%4];"
                 : "=r"(r[0]), "=r"(r[1]), "=r"(r[2]), "=r"(r[3]) : "r"(addr));
}
__device__ __forceinline__ void mma16816(float* d, const uint32_t* a, const uint32_t* b) {
    asm volatile(
        "mma.sync.aligned.m16n8k16.row.col.f32.bf16.bf16.f32 "
        "{%0,%1,%2,%3}, {%4,%5,%6,%7}, {%8,%9}, {%0,%1,%2,%3};"
        : "+f"(d[0]), "+f"(d[1]), "+f"(d[2]), "+f"(d[3])
        : "r"(a[0]), "r"(a[1]), "r"(a[2]), "r"(a[3]), "r"(b[0]), "r"(b[1]));
}

// ---------------------------------------------------------------------------
// K0: bias gather/transpose
// ---------------------------------------------------------------------------
__global__ void bias_gather_kernel(const float* __restrict__ table) {
    __shared__ float tile[32][241];
    const int ij0 = blockIdx.x * 32;
    const int tt0 = blockIdx.y * 240;
    const int tid = threadIdx.x;

    for (int e = tid; e < 32 * 240; e += 256) {
        int ii = e / 240, tt = e % 240;
        int ij = ij0 + ii;
        int a = ij / LTOK, b = ij % LTOK;
        tile[ii][tt] = table[(size_t)posidx(a, b) * (TOW * NHEAD) + tt0 + tt];
    }
    __syncthreads();
    for (int e = tid; e < 32 * 240; e += 256) {
        int tt = e / 32, c = e % 32;
        g_bias[(size_t)(tt0 + tt) * (LTOK * LTOK) + ij0 + c] = tile[c][tt];
    }
}

// ---------------------------------------------------------------------------
// HMMA GEMM: C[m][n] = sum_k A[m][k]*B[n][k] + bias[n]
// mma.sync m16n8k16 bf16, 3-term split (AhBh + AhBl + AlBh), fp32 acc.
// Block: 128 thr (4 warps, 2x2 grid of 32x32 warp tiles), BM=64 M-tile,
// A hi/lo staged once (full K=192), loop NT N-tiles of 64 staging B hi/lo.
// smem rows: 192 bf16 + 8 pad = 400B stride -> ldmatrix conflict-free.
// MODE 1: A=x, scatter to g_qkv.  MODE 0: A=g_att, row-major C.
// ---------------------------------------------------------------------------
#define ROWB  400                       // bytes per smem row (200 halves)
#define AH_OFF 0
#define AL_OFF (64 * ROWB)              // 25600
#define BH_OFF (2 * 64 * ROWB)          // 51200
#define BL_OFF (3 * 64 * ROWB)          // 76800
#define SM_TOTAL (4 * 64 * ROWB)        // 102400

template <int NT, int MODE>
__global__ __launch_bounds__(128)
void tc_gemm(const float* __restrict__ Ain,
             const float* __restrict__ B,
             const float* __restrict__ bias,
             float* __restrict__ C) {
    extern __shared__ __align__(16) char sm[];
    const uint32_t smb = smem_u32(sm);
    const int tid = threadIdx.x;
    const int wid = tid >> 5, lane = tid & 31;
    const float* A = (MODE == 0) ? g_att : Ain;
    const int m0 = blockIdx.x * 64;

    // ---- A fill (once): 64 x 192 f32 -> bf16 hi/lo planes ----
    for (int e = tid; e < 64 * 48; e += 128) {
        int m = e / 48, k4 = e % 48;
        float4 v = *reinterpret_cast<const float4*>(A + (size_t)(m0 + m) * 192 + k4 * 4);
        float hx = __bfloat162float(__float2bfloat16(v.x));
        float hy = __bfloat162float(__float2bfloat16(v.y));
        float hz = __bfloat162float(__float2bfloat16(v.z));
        float hw = __bfloat162float(__float2bfloat16(v.w));
        uint32_t off = m * ROWB + k4 * 8;
        *reinterpret_cast<uint2*>(sm + AH_OFF + off) =
            make_uint2(pack2(hx, hy), pack2(hz, hw));
        *reinterpret_cast<uint2*>(sm + AL_OFF + off) =
            make_uint2(pack2(v.x - hx, v.y - hy), pack2(v.z - hz, v.w - hw));
    }

    const int wm = wid & 1, wn = wid >> 1;      // warp tile (32m x 32n)
    const int gid = lane >> 2, qid = lane & 3;  // mma thread coords
    const int g = lane >> 3, r8 = lane & 7;     // ldmatrix lane coords

    for (int nt = 0; nt < NT; nt++) {
        if (nt) __syncthreads();
        // ---- B tile fill: 64 x 192 ----
        for (int e = tid; e < 64 * 48; e += 128) {
            int n = e / 48, k4 = e % 48;
            float4 v = *reinterpret_cast<const float4*>(
                B + (size_t)(nt * 64 + n) * 192 + k4 * 4);
            float hx = __bfloat162float(__float2bfloat16(v.x));
            float hy = __bfloat162float(__float2bfloat16(v.y));
            float hz = __bfloat162float(__float2bfloat16(v.z));
            float hw = __bfloat162float(__float2bfloat16(v.w));
            uint32_t off = n * ROWB + k4 * 8;
            *reinterpret_cast<uint2*>(sm + BH_OFF + off) =
                make_uint2(pack2(hx, hy), pack2(hz, hw));
            *reinterpret_cast<uint2*>(sm + BL_OFF + off) =
                make_uint2(pack2(v.x - hx, v.y - hy), pack2(v.z - hz, v.w - hw));
        }
        __syncthreads();

        float acc[2][4][4];
#pragma unroll
        for (int i = 0; i < 2; i++)
#pragma unroll
            for (int j = 0; j < 4; j++)
#pragma unroll
                for (int c = 0; c < 4; c++) acc[i][j][c] = 0.0f;

#pragma unroll 3
        for (int ks = 0; ks < 12; ks++) {
            const int k0 = ks * 16;
            // A fragments (hi/lo), 2 m16 tiles each.
            // ldmatrix lane->addr: row = base + r8 + (g&1)*8, k = k0 + (g>=2)*8
            uint32_t ah[2][4], al[2][4];
#pragma unroll
            for (int mt = 0; mt < 2; mt++) {
                uint32_t row = wm * 32 + mt * 16 + r8 + (g & 1) * 8;
                uint32_t koff = (k0 + (g >> 1) * 8) * 2;
                ldsm4(ah[mt], smb + AH_OFF + row * ROWB + koff);
                ldsm4(al[mt], smb + AL_OFF + row * ROWB + koff);
            }
            // B fragments (hi/lo): 2 x ldmatrix.x4, each covers two n8 tiles.
            // lane->addr: row = nb + r8 + (g>=2)*8, k = k0 + (g&1)*8
            uint32_t bh[4][2], bl[4][2];
#pragma unroll
            for (int pr = 0; pr < 2; pr++) {
                uint32_t row = wn * 32 + pr * 16 + r8 + (g >> 1) * 8;
                uint32_t koff = (k0 + (g & 1) * 8) * 2;
                uint32_t th[4], tl[4];
                ldsm4(th, smb + BH_OFF + row * ROWB + koff);
                ldsm4(tl, smb + BL_OFF + row * ROWB + koff);
                bh[pr * 2 + 0][0] = th[0]; bh[pr * 2 + 0][1] = th[1];
                bh[pr * 2 + 1][0] = th[2]; bh[pr * 2 + 1][1] = th[3];
                bl[pr * 2 + 0][0] = tl[0]; bl[pr * 2 + 0][1] = tl[1];
                bl[pr * 2 + 1][0] = tl[2]; bl[pr * 2 + 1][1] = tl[3];
            }
#pragma unroll
            for (int mt = 0; mt < 2; mt++)
#pragma unroll
                for (int ntn = 0; ntn < 4; ntn++) {
                    mma16816(acc[mt][ntn], ah[mt], bh[ntn]);
                    mma16816(acc[mt][ntn], ah[mt], bl[ntn]);
                    mma16816(acc[mt][ntn], al[mt], bh[ntn]);
                }
        }

        // ---- epilogue: acc + bias -> destination ----
        const int cbase = nt * 64 + wn * 32;
#pragma unroll
        for (int ntn = 0; ntn < 4; ntn++) {
            const int c = cbase + ntn * 8 + qid * 2;
            const float2 bv = *reinterpret_cast<const float2*>(bias + c);
#pragma unroll
            for (int mt = 0; mt < 2; mt++) {
#pragma unroll
                for (int half = 0; half < 2; half++) {
                    const int m = m0 + wm * 32 + mt * 16 + gid + half * 8;
                    float2 o;
                    o.x = acc[mt][ntn][half * 2 + 0] + bv.x;
                    o.y = acc[mt][ntn][half * 2 + 1] + bv.y;
                    if (MODE == 0) {
                        *reinterpret_cast<float2*>(C + (size_t)m * DIM + c) = o;
                    } else {
                        const int w = m / LTOK, l = m % LTOK;
                        const int t = c / DIM, hh = (c % DIM) / HD, d = c % HD;
                        *reinterpret_cast<float2*>(
                            g_qkv + ((((size_t)w * 3 + t) * NHEAD + hh) * LTOK + l) * HD + d) = o;
                    }
                }
            }
        }
    }
}

// ---------------------------------------------------------------------------
// K2: fused attention (exact R2 version).
// ---------------------------------------------------------------------------
__global__ __launch_bounds__(160)
void attn_kernel(const float* __restrict__ mask) {
    __shared__ float4 ks4[LTOK * 8];
    __shared__ float4 vs4[LTOK * 8];

    const int bx = blockIdx.x;
    const int tow = bx / NHEAD;
    const int h = bx % NHEAD;
    const int tid = threadIdx.x;

    for (int wrep = 0; wrep < 3; wrep++) {
        const int w = tow + wrep * TOW;
        const float4* kg = reinterpret_cast<const float4*>(
            g_qkv + (((size_t)w * 3 + 1) * NHEAD + h) * (LTOK * HD));
        const float4* vg = reinterpret_cast<const float4*>(
            g_qkv + (((size_t)w * 3 + 2) * NHEAD + h) * (LTOK * HD));

        __syncthreads();
        for (int e = tid; e < LTOK * 8; e += 160) {
            ks4[e] = kg[e];
            vs4[e] = vg[e];
        }
        __syncthreads();

        if (tid < LTOK) {
            const int i = tid;
            const float4* qg = reinterpret_cast<const float4*>(
                g_qkv + (((size_t)w * 3 + 0) * NHEAD + h) * (LTOK * HD) + i * HD);
            float4 q[8];
#pragma unroll
            for (int d = 0; d < 8; d++) {
                q[d] = qg[d];
                q[d].x *= SCALE; q[d].y *= SCALE; q[d].z *= SCALE; q[d].w *= SCALE;
            }
            const float4* brow = reinterpret_cast<const float4*>(
                g_bias + ((size_t)tow * NHEAD + h) * (LTOK * LTOK) + i * LTOK);
            const float4* mrow = reinterpret_cast<const float4*>(
                mask + ((size_t)w * LTOK + i) * LTOK);

            float4 acc[8];
#pragma unroll
            for (int d = 0; d < 8; d++) acc[d] = make_float4(0.f, 0.f, 0.f, 0.f);
            float lsum = 0.0f;

            for (int j4 = 0; j4 < LTOK / 4; j4++) {
                float4 b4 = brow[j4];
                float4 m4 = mrow[j4];
                float bm[4] = {b4.x + m4.x, b4.y + m4.y, b4.z + m4.z, b4.w + m4.w};
#pragma unroll
                for (int u = 0; u < 4; u++) {
                    const int j = j4 * 4 + u;
                    const float4* kr = &ks4[j * 8];
                    float s0 = 0.f, s1 = 0.f, s2 = 0.f, s3 = 0.f;
#pragma unroll
                    for (int d = 0; d < 8; d += 2) {
                        float4 k0 = kr[d], k1 = kr[d + 1];
                        s0 += q[d].x * k0.x + q[d].y * k0.y;
                        s1 += q[d].z * k0.z + q[d].w * k0.w;
                        s2 += q[d + 1].x * k1.x + q[d + 1].y * k1.y;
                        s3 += q[d + 1].z * k1.z + q[d + 1].w * k1.w;
                    }
                    float p = __expf((s0 + s1) + (s2 + s3) + bm[u]);
                    lsum += p;
                    const float4* vr = &vs4[j * 8];
#pragma unroll
                    for (int d = 0; d < 8; d++) {
                        float4 vv = vr[d];
                        acc[d].x += p * vv.x;
                        acc[d].y += p * vv.y;
                        acc[d].z += p * vv.z;
                        acc[d].w += p * vv.w;
                    }
                }
            }
            const float rinv = 1.0f / lsum;
            float4* orow = reinterpret_cast<float4*>(
                g_att + ((size_t)w * LTOK + i) * DIM + h * HD);
#pragma unroll
            for (int d = 0; d < 8; d++) {
                float4 o = acc[d];
                o.x *= rinv; o.y *= rinv; o.z *= rinv; o.w *= rinv;
                orow[d] = o;
            }
        }
    }
}

// ---------------------------------------------------------------------------
// Launch. Inputs: 0 x, 1 mask, 2 w1, 3 b1, 4 w2, 5 b2, 6 bias_table
// ---------------------------------------------------------------------------
extern "C" void kernel_launch(void* const* d_in, const int* in_sizes, int n_in,
                              void* d_out, int out_size) {
    const float* x     = (const float*)d_in[0];
    const float* mask  = (const float*)d_in[1];
    const float* w1    = (const float*)d_in[2];
    const float* b1    = (const float*)d_in[3];
    const float* w2    = (const float*)d_in[4];
    const float* b2    = (const float*)d_in[5];
    const float* table = (const float*)d_in[6];
    float* out = (float*)d_out;

    static bool attr_done = false;
    if (!attr_done) {
        cudaFuncSetAttribute(tc_gemm<9, 1>,
                             cudaFuncAttributeMaxDynamicSharedMemorySize, SM_TOTAL);
        cudaFuncSetAttribute(tc_gemm<3, 0>,
                             cudaFuncAttributeMaxDynamicSharedMemorySize, SM_TOTAL);
        attr_done = true;
    }

    bias_gather_kernel<<<dim3(648, 6), 256>>>(table);
    tc_gemm<9, 1><<<1620, 128, SM_TOTAL>>>(x, w1, b1, nullptr);      // qkv proj
    attn_kernel<<<TOW * NHEAD, 160>>>(mask);
    tc_gemm<3, 0><<<1620, 128, SM_TOTAL>>>(nullptr, w2, b2, out);    // out proj
}